// round 15
// baseline (speedup 1.0000x reference)
#include <cuda_runtime.h>
#include <cuda_bf16.h>
#include <math.h>

// ---------------- Problem constants ----------------
#define NNODES 50000
#define NEDGES 800000
#define INDIM  256
#define HDIM   96
#define OUTDIM 40
#define H4     24
#define BN_EPSF 1e-5f

// ---------------- Scratch (device globals) ----------------
__device__ int   g_cnt [NNODES];
__device__ int   g_fill[NNODES];
__device__ int   g_rowptr[NNODES + 1];
__device__ float g_dinv[NNODES];
__device__ int   g_row [NEDGES];
__device__ int   g_col [NEDGES];
__device__ __align__(16) long long g_csr[NEDGES];   // {norm:f32 hi, row:int32 lo}
__device__ __align__(16) float g_x0  [NNODES * HDIM];
__device__ __align__(16) float g_xcur[NNODES * HDIM];
__device__ __align__(16) float g_agg [NNODES * HDIM];
__device__ float g_sums[2 * HDIM];
__device__ int   g_is64;

// ---------------- f32x2 helpers ----------------
__device__ __forceinline__ unsigned long long fma2(
    unsigned long long a, unsigned long long b, unsigned long long c) {
    unsigned long long d;
    asm("fma.rn.f32x2 %0, %1, %2, %3;" : "=l"(d) : "l"(a), "l"(b), "l"(c));
    return d;
}
__device__ __forceinline__ unsigned long long pack2(float lo, float hi) {
    unsigned long long d;
    asm("mov.b64 %0, {%1, %2};" : "=l"(d) : "f"(lo), "f"(hi));
    return d;
}
__device__ __forceinline__ void unpack2(unsigned long long v, float& lo, float& hi) {
    asm("mov.b64 {%0, %1}, %2;" : "=f"(lo), "=f"(hi) : "l"(v));
}

// ---------------- setup: detect dtype + zero counters (launch 0) -----------
__global__ void detect_zero(const void* p) {
    int i = blockIdx.x * 256 + threadIdx.x;
    if (i < NNODES) g_cnt[i] = 0;
    if (blockIdx.x == 0) {
        const int* q = (const int*)p;
        __shared__ int s;
        if (threadIdx.x == 0) s = 0;
        __syncthreads();
        int nz = 0;
        for (int k = threadIdx.x; k < 1024; k += 256) nz |= q[2 * k + 1];
        if (nz) atomicOr(&s, 1);
        __syncthreads();
        if (threadIdx.x == 0) g_is64 = (s == 0) ? 1 : 0;
    }
}

// convert to int32 and count in-degrees (launch 1)
__global__ void convert_idx(const void* p) {
    int e = blockIdx.x * 256 + threadIdx.x;
    if (e >= NEDGES) return;
    int r, c;
    if (g_is64) {
        const long long* q = (const long long*)p;
        r = (int)q[e];
        c = (int)q[(long long)NEDGES + e];
    } else {
        const int* q = (const int*)p;
        r = q[e];
        c = q[NEDGES + e];
    }
    g_row[e] = r;
    g_col[e] = c;
    atomicAdd(&g_cnt[c], 1);
}

// single-block: dinv + exclusive scan + zero fill (launch 2)
#define SCAN_PER 49
__global__ __launch_bounds__(1024) void scan_dinv() {
    __shared__ int part[1024];
    int t = threadIdx.x;
    int base = t * SCAN_PER;
    int sum = 0;
    for (int i = 0; i < SCAN_PER; i++) {
        int idx = base + i;
        if (idx < NNODES) {
            int c = g_cnt[idx];
            sum += c;
            g_dinv[idx] = rsqrtf((float)(c + 1));
        }
    }
    part[t] = sum;
    __syncthreads();
    for (int d = 1; d < 1024; d <<= 1) {
        int v = (t >= d) ? part[t - d] : 0;
        __syncthreads();
        part[t] += v;
        __syncthreads();
    }
    int run = (t > 0) ? part[t - 1] : 0;
    for (int i = 0; i < SCAN_PER; i++) {
        int idx = base + i;
        if (idx <= NNODES) g_rowptr[idx] = run;
        if (idx < NNODES) {
            run += g_cnt[idx];
            g_fill[idx] = 0;
        }
    }
}

// ---------------- fc1 (launch 3 -> profiled slot) ---------------------------
// relu(X @ W + b) -> g_x0. 256 rows x 96 cols per CTA, 256 threads.
// Thread tile: 16 rows (8 f32x2 pairs) x 6 cols. K chunks of 16.
// Per kk: 4 LDS.128 (A) + 6 LDS.64 (W dup) -> 48 FFMA2 (ratio 4.8).
#define KCH 16
#define RSTR 260    // row-dim stride in As (floats); 260*4=1040B = 65*16 ✓
__global__ __launch_bounds__(256) void fc1_gemm(
    const float* __restrict__ X, const float* __restrict__ W,
    const float* __restrict__ b)
{
    __shared__ __align__(16) float As[KCH * RSTR];              // [k][r]
    __shared__ __align__(16) unsigned long long Ws2[KCH * HDIM];// [k][c] dup
    int tid = threadIdx.x;
    int tx = tid & 15, ty = tid >> 4;       // ty 0..15 -> rows ty*16..+15
    int rowbase = blockIdx.x * 256;
    unsigned long long acc[8][6];
    #pragma unroll
    for (int p = 0; p < 8; p++)
        #pragma unroll
        for (int j = 0; j < 6; j++) acc[p][j] = 0ULL;

    for (int kc = 0; kc < INDIM; kc += KCH) {
        // stage A transposed: 256 rows x 16 k = 1024 float4, 4/thread
        #pragma unroll
        for (int i = 0; i < 4; i++) {
            int idx = tid + i * 256;
            int r = idx >> 2, kq = idx & 3;
            int gr = rowbase + r;
            float4 v = make_float4(0.f, 0.f, 0.f, 0.f);
            if (gr < NNODES)
                v = *(const float4*)(X + (size_t)gr * INDIM + kc + kq * 4);
            As[(kq * 4 + 0) * RSTR + r] = v.x;
            As[(kq * 4 + 1) * RSTR + r] = v.y;
            As[(kq * 4 + 2) * RSTR + r] = v.z;
            As[(kq * 4 + 3) * RSTR + r] = v.w;
        }
        // stage W duplicated: 16*96 = 1536 entries, 6/thread
        #pragma unroll
        for (int i = 0; i < 6; i++) {
            int idx = tid + i * 256;
            float w = W[kc * HDIM + idx];
            Ws2[idx] = pack2(w, w);
        }
        __syncthreads();
        #pragma unroll
        for (int kk = 0; kk < KCH; kk++) {
            ulonglong2 aa[4];
            #pragma unroll
            for (int h = 0; h < 4; h++)
                aa[h] = *(const ulonglong2*)&As[kk * RSTR + ty * 16 + h * 4];
            unsigned long long wp[6];
            #pragma unroll
            for (int j = 0; j < 6; j++)
                wp[j] = Ws2[kk * HDIM + tx + 16 * j];
            #pragma unroll
            for (int h = 0; h < 4; h++) {
                #pragma unroll
                for (int j = 0; j < 6; j++) {
                    acc[2 * h][j]     = fma2(aa[h].x, wp[j], acc[2 * h][j]);
                    acc[2 * h + 1][j] = fma2(aa[h].y, wp[j], acc[2 * h + 1][j]);
                }
            }
        }
        __syncthreads();
    }
    #pragma unroll
    for (int p = 0; p < 8; p++) {
        int r0 = rowbase + ty * 16 + 2 * p;
        #pragma unroll
        for (int j = 0; j < 6; j++) {
            int c = tx + 16 * j;
            float lo, hi;
            unpack2(acc[p][j], lo, hi);
            float bb = b[c];
            if (r0 < NNODES)     g_x0[(size_t)r0 * HDIM + c]       = fmaxf(lo + bb, 0.f);
            if (r0 + 1 < NNODES) g_x0[(size_t)(r0 + 1) * HDIM + c] = fmaxf(hi + bb, 0.f);
        }
    }
}

// CSR fill (launch 4)
__global__ void fill_csr() {
    int e = blockIdx.x * 256 + threadIdx.x;
    if (e >= NEDGES) return;
    int r = g_row[e], c = g_col[e];
    int p = g_rowptr[c] + atomicAdd(&g_fill[c], 1);
    float nrm = g_dinv[r] * g_dinv[c];
    g_csr[p] = ((long long)__float_as_int(nrm) << 32) | (unsigned int)r;
}

// ---------------- pull SpMM: h1 = 0.9*agg + 0.1*x0 -> g_agg -----------------
// 3 warps per node; each warp owns 32 features (one 128B line). Every gather
// is one fully-coalesced LDG.32 warp access. Unroll 8 for MLP.
__global__ __launch_bounds__(256) void pull_kernel(int use_x0) {
    if (blockIdx.x == 0 && threadIdx.x < 2 * HDIM) g_sums[threadIdx.x] = 0.f;
    int gw = blockIdx.x * 8 + (threadIdx.x >> 5);
    int n = gw / 3;
    if (n >= NNODES) return;
    int fo = (gw - 3 * n) * 32 + (threadIdx.x & 31);
    int s = __ldg(&g_rowptr[n]), e = __ldg(&g_rowptr[n + 1]);
    float di = __ldg(&g_dinv[n]);
    float sl = di * di;
    const float* xc = use_x0 ? g_x0 : g_xcur;
    float acc = sl * __ldg(xc + (size_t)n * HDIM + fo);
    int p = s;
    for (; p + 8 <= e; p += 8) {
        long long v[8];
        #pragma unroll
        for (int u = 0; u < 8; u++) v[u] = __ldg(&g_csr[p + u]);
        float x[8];
        #pragma unroll
        for (int u = 0; u < 8; u++)
            x[u] = __ldg(xc + (size_t)(int)v[u] * HDIM + fo);
        #pragma unroll
        for (int u = 0; u < 8; u++)
            acc = fmaf(__int_as_float((int)(v[u] >> 32)), x[u], acc);
    }
    for (; p < e; p++) {
        long long v0 = __ldg(&g_csr[p]);
        float xv = __ldg(xc + (size_t)(int)v0 * HDIM + fo);
        acc = fmaf(__int_as_float((int)(v0 >> 32)), xv, acc);
    }
    float x0v = __ldg(g_x0 + (size_t)n * HDIM + fo);
    g_agg[(size_t)n * HDIM + fo] = fmaf(0.9f, acc, 0.1f * x0v);
}

// ---------------- conv: h2 = (1-B)*h1 + B*(h1@W), fused BN stats ------------
// Same 256-thread / 256-row / 16x6 tiling as fc1; K = 96 in chunks of 16.
__global__ __launch_bounds__(256) void conv_gemm(
    const float* __restrict__ W, float betaL)
{
    __shared__ __align__(16) float As[KCH * RSTR];
    __shared__ __align__(16) unsigned long long Ws2[KCH * HDIM];
    __shared__ float bsum[HDIM], bsq[HDIM];
    int tid = threadIdx.x;
    int tx = tid & 15, ty = tid >> 4;
    int rowbase = blockIdx.x * 256;
    if (tid < HDIM) { bsum[tid] = 0.f; bsq[tid] = 0.f; }
    unsigned long long acc[8][6];
    #pragma unroll
    for (int p = 0; p < 8; p++)
        #pragma unroll
        for (int j = 0; j < 6; j++) acc[p][j] = 0ULL;

    for (int kc = 0; kc < HDIM; kc += KCH) {
        #pragma unroll
        for (int i = 0; i < 4; i++) {
            int idx = tid + i * 256;
            int r = idx >> 2, kq = idx & 3;
            int gr = rowbase + r;
            float4 v = make_float4(0.f, 0.f, 0.f, 0.f);
            if (gr < NNODES)
                v = *(const float4*)(g_agg + (size_t)gr * HDIM + kc + kq * 4);
            As[(kq * 4 + 0) * RSTR + r] = v.x;
            As[(kq * 4 + 1) * RSTR + r] = v.y;
            As[(kq * 4 + 2) * RSTR + r] = v.z;
            As[(kq * 4 + 3) * RSTR + r] = v.w;
        }
        #pragma unroll
        for (int i = 0; i < 6; i++) {
            int idx = tid + i * 256;
            float w = W[kc * HDIM + idx];
            Ws2[idx] = pack2(w, w);
        }
        __syncthreads();
        #pragma unroll
        for (int kk = 0; kk < KCH; kk++) {
            ulonglong2 aa[4];
            #pragma unroll
            for (int h = 0; h < 4; h++)
                aa[h] = *(const ulonglong2*)&As[kk * RSTR + ty * 16 + h * 4];
            unsigned long long wp[6];
            #pragma unroll
            for (int j = 0; j < 6; j++)
                wp[j] = Ws2[kk * HDIM + tx + 16 * j];
            #pragma unroll
            for (int h = 0; h < 4; h++) {
                #pragma unroll
                for (int j = 0; j < 6; j++) {
                    acc[2 * h][j]     = fma2(aa[h].x, wp[j], acc[2 * h][j]);
                    acc[2 * h + 1][j] = fma2(aa[h].y, wp[j], acc[2 * h + 1][j]);
                }
            }
        }
        __syncthreads();
    }
    float ob = 1.0f - betaL;
    float s[6] = {}, q[6] = {};
    #pragma unroll
    for (int p = 0; p < 8; p++) {
        int r0 = rowbase + ty * 16 + 2 * p;
        #pragma unroll
        for (int j = 0; j < 6; j++) {
            int c = tx + 16 * j;
            float lo, hi;
            unpack2(acc[p][j], lo, hi);
            if (r0 < NNODES) {
                float h1 = g_agg[(size_t)r0 * HDIM + c];
                float h2 = fmaf(ob, h1, betaL * lo);
                g_agg[(size_t)r0 * HDIM + c] = h2;
                s[j] += h2; q[j] += h2 * h2;
            }
            if (r0 + 1 < NNODES) {
                float h1 = g_agg[(size_t)(r0 + 1) * HDIM + c];
                float h2 = fmaf(ob, h1, betaL * hi);
                g_agg[(size_t)(r0 + 1) * HDIM + c] = h2;
                s[j] += h2; q[j] += h2 * h2;
            }
        }
    }
    __syncthreads();
    #pragma unroll
    for (int j = 0; j < 6; j++) {
        int c = tx + 16 * j;
        atomicAdd(&bsum[c], s[j]);
        atomicAdd(&bsq[c], q[j]);
    }
    __syncthreads();
    if (tid < HDIM) {
        atomicAdd(&g_sums[tid], bsum[tid]);
        atomicAdd(&g_sums[HDIM + tid], bsq[tid]);
    }
}

// ---------------- BN apply + relu -> g_xcur ----------------
__global__ __launch_bounds__(256) void bn_apply(
    const float* __restrict__ gamma, const float* __restrict__ beta)
{
    __shared__ float sc[HDIM], sh[HDIM];
    int tid = threadIdx.x;
    if (tid < HDIM) {
        float s = g_sums[tid], q = g_sums[HDIM + tid];
        float mean = s * (1.0f / NNODES);
        float var  = q * (1.0f / NNODES) - mean * mean;
        float scl = gamma[tid] * rsqrtf(var + BN_EPSF);
        sc[tid] = scl;
        sh[tid] = beta[tid] - mean * scl;
    }
    __syncthreads();
    int i = blockIdx.x * 256 + tid;
    if (i >= NNODES * H4) return;
    int c = (i % H4) * 4;
    float4 v = ((const float4*)g_agg)[i];
    float4 o;
    o.x = fmaxf(fmaf(v.x, sc[c + 0], sh[c + 0]), 0.f);
    o.y = fmaxf(fmaf(v.y, sc[c + 1], sh[c + 1]), 0.f);
    o.z = fmaxf(fmaf(v.z, sc[c + 2], sh[c + 2]), 0.f);
    o.w = fmaxf(fmaf(v.w, sc[c + 3], sh[c + 3]), 0.f);
    ((float4*)g_xcur)[i] = o;
}

// ---------------- fc2: out = xcur @ W + b ----------------
__global__ __launch_bounds__(256) void fc2_gemm(
    const float* __restrict__ W, const float* __restrict__ b,
    float* __restrict__ out)
{
    __shared__ float As[64][100];
    __shared__ float Ws[HDIM][OUTDIM];
    int tid = threadIdx.x;
    int rowbase = blockIdx.x * 64;
    #pragma unroll
    for (int i = 0; i < 24; i++) {
        int idx = tid + i * 256;
        int r = idx / HDIM, c = idx - r * HDIM;
        int gr = rowbase + r;
        As[r][c] = (gr < NNODES) ? g_xcur[(size_t)gr * HDIM + c] : 0.f;
    }
    #pragma unroll
    for (int i = 0; i < 15; i++) {
        int idx = tid + i * 256;
        int k = idx / OUTDIM, c = idx - k * OUTDIM;
        Ws[k][c] = W[idx];
    }
    __syncthreads();
    int r = tid >> 2;
    int cg = tid & 3;
    float acc[10] = {};
    #pragma unroll 4
    for (int k = 0; k < HDIM; k++) {
        float a = As[r][k];
        #pragma unroll
        for (int j = 0; j < 10; j++)
            acc[j] = fmaf(a, Ws[k][cg * 10 + j], acc[j]);
    }
    int gr = rowbase + r;
    if (gr < NNODES) {
        #pragma unroll
        for (int j = 0; j < 10; j++)
            out[(size_t)gr * OUTDIM + cg * 10 + j] = acc[j] + b[cg * 10 + j];
    }
}

// ---------------- launch ----------------
extern "C" void kernel_launch(void* const* d_in, const int* in_sizes, int n_in,
                              void* d_out, int out_size) {
    const float* x     = (const float*)d_in[0];
    const void*  eidx  = d_in[1];
    const float* fc1w  = (const float*)d_in[2];
    const float* fc1b  = (const float*)d_in[3];
    const float* convw = (const float*)d_in[4];
    const float* gam   = (const float*)d_in[5];
    const float* bet   = (const float*)d_in[6];
    const float* fc2w  = (const float*)d_in[7];
    const float* fc2b  = (const float*)d_in[8];
    float* out = (float*)d_out;

    const int nb_node = (NNODES + 255) / 256;
    const int nb_edge = (NEDGES + 255) / 256;
    const int nb_g256 = (NNODES + 255) / 256;
    const int nb_g64  = (NNODES + 63) / 64;
    const int nb_elem = (NNODES * H4 + 255) / 256;
    const int nb_pull = (NNODES * 3 + 7) / 8;     // 3 warps/node, 8 warps/block

    detect_zero<<<nb_node, 256>>>(eidx);            // 0
    convert_idx<<<nb_edge, 256>>>(eidx);            // 1
    scan_dinv<<<1, 1024>>>();                       // 2
    fc1_gemm<<<nb_g256, 256>>>(x, fc1w, fc1b);      // 3  <- profiled slot
    fill_csr<<<nb_edge, 256>>>();                   // 4

    const float betas[3] = {0.40546510810f, 0.22314355131f, 0.15415067982f};
    for (int l = 0; l < 3; l++) {
        pull_kernel<<<nb_pull, 256>>>(l == 0 ? 1 : 0);
        conv_gemm<<<nb_g256, 256>>>(convw + l * HDIM * HDIM, betas[l]);
        bn_apply<<<nb_elem, 256>>>(gam + l * HDIM, bet + l * HDIM);
    }

    fc2_gemm<<<nb_g64, 256>>>(fc2w, fc2b, out);
}

// round 16
// speedup vs baseline: 1.2356x; 1.2356x over previous
#include <cuda_runtime.h>
#include <cuda_bf16.h>
#include <math.h>

// ---------------- Problem constants ----------------
#define NNODES 50000
#define NEDGES 800000
#define INDIM  256
#define HDIM   96
#define OUTDIM 40
#define H4     24
#define BN_EPSF 1e-5f

// ---------------- Scratch (device globals) ----------------
__device__ int   g_cnt [NNODES];
__device__ int   g_fill[NNODES];
__device__ int   g_rowptr[NNODES + 1];
__device__ float g_dinv[NNODES];
__device__ int   g_row [NEDGES];
__device__ int   g_col [NEDGES];
__device__ __align__(16) long long g_csr[NEDGES];   // {norm:f32 hi, row:int32 lo}
__device__ __align__(16) float g_x0  [NNODES * HDIM];
__device__ __align__(16) float g_xcur[NNODES * HDIM];
__device__ __align__(16) float g_agg [NNODES * HDIM];
__device__ float g_sums[2 * HDIM];
__device__ int   g_is64;

// ---------------- f32x2 helpers ----------------
__device__ __forceinline__ unsigned long long fma2(
    unsigned long long a, unsigned long long b, unsigned long long c) {
    unsigned long long d;
    asm("fma.rn.f32x2 %0, %1, %2, %3;" : "=l"(d) : "l"(a), "l"(b), "l"(c));
    return d;
}
__device__ __forceinline__ unsigned long long pack2(float lo, float hi) {
    unsigned long long d;
    asm("mov.b64 %0, {%1, %2};" : "=l"(d) : "f"(lo), "f"(hi));
    return d;
}
__device__ __forceinline__ void unpack2(unsigned long long v, float& lo, float& hi) {
    asm("mov.b64 {%0, %1}, %2;" : "=f"(lo), "=f"(hi) : "l"(v));
}

// ---------------- setup: detect dtype + zero counters (launch 0) -----------
__global__ void detect_zero(const void* p) {
    int i = blockIdx.x * 256 + threadIdx.x;
    if (i < NNODES) g_cnt[i] = 0;
    if (blockIdx.x == 0) {
        const int* q = (const int*)p;
        __shared__ int s;
        if (threadIdx.x == 0) s = 0;
        __syncthreads();
        int nz = 0;
        for (int k = threadIdx.x; k < 1024; k += 256) nz |= q[2 * k + 1];
        if (nz) atomicOr(&s, 1);
        __syncthreads();
        if (threadIdx.x == 0) g_is64 = (s == 0) ? 1 : 0;
    }
}

// convert to int32 and count in-degrees (launch 1)
__global__ void convert_idx(const void* p) {
    int e = blockIdx.x * 256 + threadIdx.x;
    if (e >= NEDGES) return;
    int r, c;
    if (g_is64) {
        const long long* q = (const long long*)p;
        r = (int)q[e];
        c = (int)q[(long long)NEDGES + e];
    } else {
        const int* q = (const int*)p;
        r = q[e];
        c = q[NEDGES + e];
    }
    g_row[e] = r;
    g_col[e] = c;
    atomicAdd(&g_cnt[c], 1);
}

// single-block: dinv + exclusive scan + zero fill (launch 2)
#define SCAN_PER 49
__global__ __launch_bounds__(1024) void scan_dinv() {
    __shared__ int part[1024];
    int t = threadIdx.x;
    int base = t * SCAN_PER;
    int sum = 0;
    for (int i = 0; i < SCAN_PER; i++) {
        int idx = base + i;
        if (idx < NNODES) {
            int c = g_cnt[idx];
            sum += c;
            g_dinv[idx] = rsqrtf((float)(c + 1));
        }
    }
    part[t] = sum;
    __syncthreads();
    for (int d = 1; d < 1024; d <<= 1) {
        int v = (t >= d) ? part[t - d] : 0;
        __syncthreads();
        part[t] += v;
        __syncthreads();
    }
    int run = (t > 0) ? part[t - 1] : 0;
    for (int i = 0; i < SCAN_PER; i++) {
        int idx = base + i;
        if (idx <= NNODES) g_rowptr[idx] = run;
        if (idx < NNODES) {
            run += g_cnt[idx];
            g_fill[idx] = 0;
        }
    }
}

// ---------------- fc1 (launch 3 -> profiled slot): champion config ----------
// relu(X @ W + b) -> g_x0. 128 rows x 96 cols, 256 threads, 8x6 f32x2 tile,
// in-loop W pack. (Measured 80.9us @ occ 21.5% in R8.)
#define APAD 130
__global__ __launch_bounds__(256) void fc1_gemm(
    const float* __restrict__ X, const float* __restrict__ W,
    const float* __restrict__ b)
{
    __shared__ __align__(16) float As[32 * APAD];   // [k][r] transposed
    __shared__ __align__(16) float Ws[32 * HDIM];   // [k][c]
    int tid = threadIdx.x;
    int tx = tid & 15, ty = tid >> 4;
    int rowbase = blockIdx.x * 128;
    unsigned long long acc[4][6];
    #pragma unroll
    for (int p = 0; p < 4; p++)
        #pragma unroll
        for (int j = 0; j < 6; j++) acc[p][j] = 0ULL;

    for (int kc = 0; kc < INDIM; kc += 32) {
        #pragma unroll
        for (int i = 0; i < 4; i++) {
            int idx = tid + i * 256;
            int r = idx >> 3, kq = idx & 7;
            int gr = rowbase + r;
            float4 v = make_float4(0.f, 0.f, 0.f, 0.f);
            if (gr < NNODES)
                v = *(const float4*)(X + (size_t)gr * INDIM + kc + kq * 4);
            As[(kq * 4 + 0) * APAD + r] = v.x;
            As[(kq * 4 + 1) * APAD + r] = v.y;
            As[(kq * 4 + 2) * APAD + r] = v.z;
            As[(kq * 4 + 3) * APAD + r] = v.w;
        }
        #pragma unroll
        for (int i = 0; i < 12; i++) {
            int idx = tid + i * 256;
            Ws[idx] = W[kc * HDIM + idx];
        }
        __syncthreads();
        #pragma unroll 8
        for (int kk = 0; kk < 32; kk++) {
            unsigned long long a[4], wp[6];
            #pragma unroll
            for (int p = 0; p < 4; p++)
                a[p] = *(const unsigned long long*)&As[kk * APAD + ty * 8 + 2 * p];
            #pragma unroll
            for (int j = 0; j < 6; j++) {
                float w = Ws[kk * HDIM + tx + 16 * j];
                wp[j] = pack2(w, w);
            }
            #pragma unroll
            for (int p = 0; p < 4; p++)
                #pragma unroll
                for (int j = 0; j < 6; j++)
                    acc[p][j] = fma2(a[p], wp[j], acc[p][j]);
        }
        __syncthreads();
    }
    #pragma unroll
    for (int p = 0; p < 4; p++) {
        int r0 = rowbase + ty * 8 + 2 * p;
        #pragma unroll
        for (int j = 0; j < 6; j++) {
            int c = tx + 16 * j;
            float lo, hi;
            unpack2(acc[p][j], lo, hi);
            float bb = b[c];
            if (r0 < NNODES)
                g_x0[(size_t)r0 * HDIM + c] = fmaxf(lo + bb, 0.f);
            if (r0 + 1 < NNODES)
                g_x0[(size_t)(r0 + 1) * HDIM + c] = fmaxf(hi + bb, 0.f);
        }
    }
}

// CSR fill (launch 4)
__global__ void fill_csr() {
    int e = blockIdx.x * 256 + threadIdx.x;
    if (e >= NEDGES) return;
    int r = g_row[e], c = g_col[e];
    int p = g_rowptr[c] + atomicAdd(&g_fill[c], 1);
    float nrm = g_dinv[r] * g_dinv[c];
    g_csr[p] = ((long long)__float_as_int(nrm) << 32) | (unsigned int)r;
}

// ---------------- pull SpMM (champion scalar version) -----------------------
// warp per node; lane handles features {lane, lane+32, lane+64}; unroll 2.
__global__ __launch_bounds__(256) void pull_kernel(int use_x0) {
    int gtid = blockIdx.x * 256 + threadIdx.x;
    if (blockIdx.x == 0 && threadIdx.x < 2 * HDIM) g_sums[threadIdx.x] = 0.f;
    int n = gtid >> 5;
    if (n >= NNODES) return;
    int lane = gtid & 31;
    int s = g_rowptr[n], e = g_rowptr[n + 1];
    float di = g_dinv[n];
    float sl = di * di;
    const float* xcur = use_x0 ? g_x0 : g_xcur;
    const float* xc = xcur + (size_t)n * HDIM;
    float a0 = sl * xc[lane];
    float a1 = sl * xc[lane + 32];
    float a2 = sl * xc[lane + 64];
    int p = s;
    for (; p + 2 <= e; p += 2) {
        long long v0 = g_csr[p], v1 = g_csr[p + 1];
        int r0 = (int)v0, r1 = (int)v1;
        float n0 = __int_as_float((int)(v0 >> 32));
        float n1 = __int_as_float((int)(v1 >> 32));
        const float* x0p = xcur + (size_t)r0 * HDIM;
        const float* x1p = xcur + (size_t)r1 * HDIM;
        float b0 = x0p[lane], b1 = x0p[lane + 32], b2 = x0p[lane + 64];
        float c0 = x1p[lane], c1 = x1p[lane + 32], c2 = x1p[lane + 64];
        a0 = fmaf(n0, b0, a0); a1 = fmaf(n0, b1, a1); a2 = fmaf(n0, b2, a2);
        a0 = fmaf(n1, c0, a0); a1 = fmaf(n1, c1, a1); a2 = fmaf(n1, c2, a2);
    }
    if (p < e) {
        long long v0 = g_csr[p];
        int r0 = (int)v0;
        float n0 = __int_as_float((int)(v0 >> 32));
        const float* x0p = xcur + (size_t)r0 * HDIM;
        a0 = fmaf(n0, x0p[lane], a0);
        a1 = fmaf(n0, x0p[lane + 32], a1);
        a2 = fmaf(n0, x0p[lane + 64], a2);
    }
    const float* x0n = g_x0 + (size_t)n * HDIM;
    float* ag = g_agg + (size_t)n * HDIM;
    ag[lane]      = fmaf(0.9f, a0, 0.1f * x0n[lane]);
    ag[lane + 32] = fmaf(0.9f, a1, 0.1f * x0n[lane + 32]);
    ag[lane + 64] = fmaf(0.9f, a2, 0.1f * x0n[lane + 64]);
}

// ---------------- conv: h2 = (1-B)*h1 + B*(h1@W), fused BN stats ------------
// Champion config: 128 rows, 256 threads, 8x6 f32x2, in-loop pack.
__global__ __launch_bounds__(256) void conv_gemm(
    const float* __restrict__ W, float betaL)
{
    __shared__ __align__(16) float As[32 * APAD];
    __shared__ __align__(16) float Ws[32 * HDIM];
    __shared__ float bsum[HDIM], bsq[HDIM];
    int tid = threadIdx.x;
    int tx = tid & 15, ty = tid >> 4;
    int rowbase = blockIdx.x * 128;
    if (tid < HDIM) { bsum[tid] = 0.f; bsq[tid] = 0.f; }
    unsigned long long acc[4][6];
    #pragma unroll
    for (int p = 0; p < 4; p++)
        #pragma unroll
        for (int j = 0; j < 6; j++) acc[p][j] = 0ULL;

    for (int kc = 0; kc < HDIM; kc += 32) {
        #pragma unroll
        for (int i = 0; i < 4; i++) {
            int idx = tid + i * 256;
            int r = idx >> 3, kq = idx & 7;
            int gr = rowbase + r;
            float4 v = make_float4(0.f, 0.f, 0.f, 0.f);
            if (gr < NNODES)
                v = *(const float4*)(g_agg + (size_t)gr * HDIM + kc + kq * 4);
            As[(kq * 4 + 0) * APAD + r] = v.x;
            As[(kq * 4 + 1) * APAD + r] = v.y;
            As[(kq * 4 + 2) * APAD + r] = v.z;
            As[(kq * 4 + 3) * APAD + r] = v.w;
        }
        #pragma unroll
        for (int i = 0; i < 12; i++) {
            int idx = tid + i * 256;
            Ws[idx] = W[kc * HDIM + idx];
        }
        __syncthreads();
        #pragma unroll 8
        for (int kk = 0; kk < 32; kk++) {
            unsigned long long a[4], wp[6];
            #pragma unroll
            for (int p = 0; p < 4; p++)
                a[p] = *(const unsigned long long*)&As[kk * APAD + ty * 8 + 2 * p];
            #pragma unroll
            for (int j = 0; j < 6; j++) {
                float w = Ws[kk * HDIM + tx + 16 * j];
                wp[j] = pack2(w, w);
            }
            #pragma unroll
            for (int p = 0; p < 4; p++)
                #pragma unroll
                for (int j = 0; j < 6; j++)
                    acc[p][j] = fma2(a[p], wp[j], acc[p][j]);
        }
        __syncthreads();
    }
    float ob = 1.0f - betaL;
    float s[6] = {}, q[6] = {};
    #pragma unroll
    for (int p = 0; p < 4; p++) {
        int r0 = rowbase + ty * 8 + 2 * p;
        #pragma unroll
        for (int j = 0; j < 6; j++) {
            int c = tx + 16 * j;
            float lo, hi;
            unpack2(acc[p][j], lo, hi);
            if (r0 < NNODES) {
                float h1 = g_agg[(size_t)r0 * HDIM + c];
                float h2 = fmaf(ob, h1, betaL * lo);
                g_agg[(size_t)r0 * HDIM + c] = h2;
                s[j] += h2; q[j] += h2 * h2;
            }
            if (r0 + 1 < NNODES) {
                float h1 = g_agg[(size_t)(r0 + 1) * HDIM + c];
                float h2 = fmaf(ob, h1, betaL * hi);
                g_agg[(size_t)(r0 + 1) * HDIM + c] = h2;
                s[j] += h2; q[j] += h2 * h2;
            }
        }
    }
    __syncthreads();
    #pragma unroll
    for (int j = 0; j < 6; j++) {
        int c = tx + 16 * j;
        atomicAdd(&bsum[c], s[j]);
        atomicAdd(&bsq[c], q[j]);
    }
    __syncthreads();
    if (tid < HDIM)            atomicAdd(&g_sums[tid], bsum[tid]);
    else if (tid < 2 * HDIM)   atomicAdd(&g_sums[tid], bsq[tid - HDIM]);
}

// ---------------- BN apply + relu -> g_xcur ----------------
__global__ __launch_bounds__(256) void bn_apply(
    const float* __restrict__ gamma, const float* __restrict__ beta)
{
    __shared__ float sc[HDIM], sh[HDIM];
    int tid = threadIdx.x;
    if (tid < HDIM) {
        float s = g_sums[tid], q = g_sums[HDIM + tid];
        float mean = s * (1.0f / NNODES);
        float var  = q * (1.0f / NNODES) - mean * mean;
        float scl = gamma[tid] * rsqrtf(var + BN_EPSF);
        sc[tid] = scl;
        sh[tid] = beta[tid] - mean * scl;
    }
    __syncthreads();
    int i = blockIdx.x * 256 + tid;
    if (i >= NNODES * H4) return;
    int c = (i % H4) * 4;
    float4 v = ((const float4*)g_agg)[i];
    float4 o;
    o.x = fmaxf(fmaf(v.x, sc[c + 0], sh[c + 0]), 0.f);
    o.y = fmaxf(fmaf(v.y, sc[c + 1], sh[c + 1]), 0.f);
    o.z = fmaxf(fmaf(v.z, sc[c + 2], sh[c + 2]), 0.f);
    o.w = fmaxf(fmaf(v.w, sc[c + 3], sh[c + 3]), 0.f);
    ((float4*)g_xcur)[i] = o;
}

// ---------------- fc2: out = xcur @ W + b ----------------
__global__ __launch_bounds__(256) void fc2_gemm(
    const float* __restrict__ W, const float* __restrict__ b,
    float* __restrict__ out)
{
    __shared__ float As[64][100];
    __shared__ float Ws[HDIM][OUTDIM];
    int tid = threadIdx.x;
    int rowbase = blockIdx.x * 64;
    #pragma unroll
    for (int i = 0; i < 24; i++) {
        int idx = tid + i * 256;
        int r = idx / HDIM, c = idx - r * HDIM;
        int gr = rowbase + r;
        As[r][c] = (gr < NNODES) ? g_xcur[(size_t)gr * HDIM + c] : 0.f;
    }
    #pragma unroll
    for (int i = 0; i < 15; i++) {
        int idx = tid + i * 256;
        int k = idx / OUTDIM, c = idx - k * OUTDIM;
        Ws[k][c] = W[idx];
    }
    __syncthreads();
    int r = tid >> 2;
    int cg = tid & 3;
    float acc[10] = {};
    #pragma unroll 4
    for (int k = 0; k < HDIM; k++) {
        float a = As[r][k];
        #pragma unroll
        for (int j = 0; j < 10; j++)
            acc[j] = fmaf(a, Ws[k][cg * 10 + j], acc[j]);
    }
    int gr = rowbase + r;
    if (gr < NNODES) {
        #pragma unroll
        for (int j = 0; j < 10; j++)
            out[(size_t)gr * OUTDIM + cg * 10 + j] = acc[j] + b[cg * 10 + j];
    }
}

// ---------------- launch ----------------
extern "C" void kernel_launch(void* const* d_in, const int* in_sizes, int n_in,
                              void* d_out, int out_size) {
    const float* x     = (const float*)d_in[0];
    const void*  eidx  = d_in[1];
    const float* fc1w  = (const float*)d_in[2];
    const float* fc1b  = (const float*)d_in[3];
    const float* convw = (const float*)d_in[4];
    const float* gam   = (const float*)d_in[5];
    const float* bet   = (const float*)d_in[6];
    const float* fc2w  = (const float*)d_in[7];
    const float* fc2b  = (const float*)d_in[8];
    float* out = (float*)d_out;

    const int nb_node = (NNODES + 255) / 256;
    const int nb_edge = (NEDGES + 255) / 256;
    const int nb_g128 = (NNODES + 127) / 128;
    const int nb_g64  = (NNODES + 63) / 64;
    const int nb_elem = (NNODES * H4 + 255) / 256;
    const int nb_pull = (NNODES * 32 + 255) / 256;

    detect_zero<<<nb_node, 256>>>(eidx);            // 0
    convert_idx<<<nb_edge, 256>>>(eidx);            // 1
    scan_dinv<<<1, 1024>>>();                       // 2
    fc1_gemm<<<nb_g128, 256>>>(x, fc1w, fc1b);      // 3  <- profiled slot
    fill_csr<<<nb_edge, 256>>>();                   // 4

    const float betas[3] = {0.40546510810f, 0.22314355131f, 0.15415067982f};
    for (int l = 0; l < 3; l++) {
        pull_kernel<<<nb_pull, 256>>>(l == 0 ? 1 : 0);
        conv_gemm<<<nb_g128, 256>>>(convw + l * HDIM * HDIM, betas[l]);
        bn_apply<<<nb_elem, 256>>>(gam + l * HDIM, bet + l * HDIM);
    }

    fc2_gemm<<<nb_g64, 256>>>(fc2w, fc2b, out);
}